// round 17
// baseline (speedup 1.0000x reference)
#include <cuda_runtime.h>
#include <cstdint>

// Tucker via time-bucketing, round 17:
//   build  = R16: packed f32x2, G=2, C in SMEM float4-q layout
//   sample = R12: lane=p shuffle engine, B=8 samples in flight,
//            w0 in regs, w1 parked per-lane in stride-33 SMEM.

#define NTIME       5000
#define NTASKS      (NTIME / 2)
#define NUM_CTAS    148
#define CTA_THREADS 512
#define WARPS       (CTA_THREADS / 32)
#define CAP         96

// ---- device scratch (zero-init at load) ----
__device__ int4 g_slot[NTIME * CAP];     // (idx, iu, ij, 0)
__device__ int  g_counts[NTIME];
__device__ int  g_ovf[4096];
__device__ int  g_ovf_cnt;
__device__ int  g_ticket;

// ---- packed f32x2 helpers ----
#define PACK2(d, lo, hi) asm("mov.b64 %0, {%1, %2};" : "=l"(d) : "f"(lo), "f"(hi))
#define UNPACK2(lo, hi, s) asm("mov.b64 {%0, %1}, %2;" : "=f"(lo), "=f"(hi) : "l"(s))
#define FMA2(acc, a, b) asm("fma.rn.f32x2 %0, %1, %2, %0;" : "+l"(acc) : "l"(a), "l"(b))

__device__ __forceinline__ uint32_t smem_u32(const void* p) {
    uint32_t a;
    asm("{ .reg .u64 t; cvta.to.shared.u64 t, %1; cvt.u32.u64 %0, t; }" : "=r"(a) : "l"(p));
    return a;
}

// ============================ scatter ============================
__global__ void scatter_kernel(const int* __restrict__ k_in,
                               const int* __restrict__ i_in,
                               const int* __restrict__ j_in, int n) {
    int x = blockIdx.x * blockDim.x + threadIdx.x;
    if (x == 0) g_ticket = 0;            // consumed by the later kernel
    if (x < n) {
        int k  = k_in[x];
        int iu = i_in[x];
        int ij = j_in[x];
        int pos = atomicAdd(&g_counts[k], 1);
        if (pos < CAP) {
            g_slot[k * CAP + pos] = make_int4(x, iu, ij, 0);
        } else {
            int o = atomicAdd(&g_ovf_cnt, 1);
            if (o < 4096) g_ovf[o] = x;
        }
    }
}

// ============================ main ============================
// SMEM (floats):
//   [0, 32768)    C as float4 q-quads: float idx ((r*8 + q/4)*32 + p)*4 + (q&3)
//                 -> 16B per (r,q4,p): conflict-free LDS.128 across lanes (=p)
//   per warp w:   32768 + wid*1056 : w1 parking, per-lane stride-33 rows
#define SM_W_OFF    32768
#define PW_FLOATS   (32 * 33)
#define SMEM_FLOATS (SM_W_OFF + WARPS * PW_FLOATS)
#define SMEM_BYTES  (SMEM_FLOATS * 4)

__global__ void __launch_bounds__(CTA_THREADS, 1)
tucker_main(const int* __restrict__ i_in, const int* __restrict__ j_in,
            const int* __restrict__ k_in,
            const float* __restrict__ U, const float* __restrict__ V,
            const float* __restrict__ T, const float* __restrict__ C,
            float* __restrict__ out)
{
    extern __shared__ float sm[];
    const int tid  = threadIdx.x;
    const int wid  = tid >> 5;
    const int lane = tid & 31;   // = p

    // stage C: C[p][q][r] -> sm[((r*8 + q/4)*32 + p)*4 + (q&3)]
    for (int idx = tid; idx < 32768; idx += CTA_THREADS) {
        int p = idx >> 10, q = (idx >> 5) & 31, r = idx & 31;
        sm[(((r * 8 + (q >> 2)) * 32 + p) << 2) + (q & 3)] = C[idx];
    }
    __syncthreads();

    // overflow slow path (expected 0 iterations) — reads C from global
    if (blockIdx.x == 0 && wid == 0 && g_ovf_cnt > 0) {
        int no = min(g_ovf_cnt, 4096);
        for (int o = 0; o < no; o++) {
            int idx = g_ovf[o];
            int iu = i_in[idx], ij = j_in[idx], ik = k_in[idx];
            float up = U[(size_t)iu * 32 + lane];     // lane = p
            float sp = 0.f;
            for (int q = 0; q < 32; q++) {
                float vq = V[(size_t)ij * 32 + q];
                float acc = 0.f;
                #pragma unroll
                for (int r4 = 0; r4 < 8; r4++) {
                    float4 c4 = *(const float4*)&C[((size_t)(lane * 32 + q)) * 32 + r4 * 4];
                    float4 t4 = *(const float4*)&T[(size_t)ik * 32 + r4 * 4];
                    acc += c4.x * t4.x + c4.y * t4.y + c4.z * t4.z + c4.w * t4.w;
                }
                sp = fmaf(vq, acc, sp);
            }
            float val = up * sp;
            #pragma unroll
            for (int off = 16; off > 0; off >>= 1)
                val += __shfl_xor_sync(0xffffffffu, val, off);
            if (lane == 0) out[idx] = val;
        }
        if (lane == 0) g_ovf_cnt = 0;    // reset for next replay
    }

    float* Wst = sm + SM_W_OFF + wid * PW_FLOATS + lane * 33;  // per-lane row

    while (true) {
        int task;
        if (lane == 0) task = atomicAdd(&g_ticket, 1);
        task = __shfl_sync(0xffffffffu, task, 0);
        if (task >= NTASKS) break;

        const int b0 = task * 2;
        int cnt0, cnt1;
        if (lane == 0) { cnt0 = g_counts[b0];     g_counts[b0]     = 0; }
        if (lane == 1) { cnt1 = g_counts[b0 + 1]; g_counts[b0 + 1] = 0; }
        cnt0 = min(__shfl_sync(0xffffffffu, cnt0, 0), CAP);
        cnt1 = min(__shfl_sync(0xffffffffu, cnt1, 1), CAP);

        // ---- W build (lane = p), packed f32x2 over q-pairs, G = 2 ----
        float w[32];                   // bucket-0 W, unpacked after build
        {
            const float tl0 = T[(size_t)b0 * 32 + lane];        // lane = r
            const float tl1 = T[(size_t)(b0 + 1) * 32 + lane];
            unsigned long long w0[16], w1[16];
            #pragma unroll
            for (int x = 0; x < 16; x++) { w0[x] = 0ULL; w1[x] = 0ULL; }

            #pragma unroll 4
            for (int r = 0; r < 32; r++) {
                float f0 = __shfl_sync(0xffffffffu, tl0, r);
                float f1 = __shfl_sync(0xffffffffu, tl1, r);
                unsigned long long tr0, tr1;
                PACK2(tr0, f0, f0);
                PACK2(tr1, f1, f1);
                const ulonglong2* crow = (const ulonglong2*)sm + (size_t)r * 256 + lane;
                #pragma unroll
                for (int q4 = 0; q4 < 8; q4++) {
                    ulonglong2 cc = crow[q4 * 32];   // 16B/lane, conflict-free
                    FMA2(w0[2*q4],     cc.x, tr0);
                    FMA2(w0[2*q4 + 1], cc.y, tr0);
                    FMA2(w1[2*q4],     cc.x, tr1);
                    FMA2(w1[2*q4 + 1], cc.y, tr1);
                }
            }

            // park w1 per-lane (stride-33, conflict-free), unpack w0 to regs
            #pragma unroll
            for (int x = 0; x < 16; x++) {
                float a, b;
                UNPACK2(a, b, w1[x]);
                Wst[2*x]     = a;
                Wst[2*x + 1] = b;
            }
            #pragma unroll
            for (int x = 0; x < 16; x++) {
                UNPACK2(w[2*x], w[2*x + 1], w0[x]);
            }
        }

        // ---- sample phase (R12 engine), B = 8 in flight ----
        #pragma unroll
        for (int g = 0; g < 2; g++) {
            if (g == 1) {
                #pragma unroll
                for (int q = 0; q < 32; q++) w[q] = Wst[q];
            }
            const int b   = b0 + g;
            const int cnt = g ? cnt1 : cnt0;

            for (int base = 0; base < cnt; base += 32) {
                const int rem = min(32, cnt - base);
                int4 s4 = g_slot[b * CAP + base + min(lane, rem - 1)];

                for (int s = 0; s < rem; s += 8) {
                    float up[8], vl[8], sp[8];
                    #pragma unroll
                    for (int x = 0; x < 8; x++) {
                        int sx = min(s + x, rem - 1);
                        int iu = __shfl_sync(0xffffffffu, s4.y, sx);
                        int ij = __shfl_sync(0xffffffffu, s4.z, sx);
                        up[x] = U[(size_t)iu * 32 + lane];   // coalesced row
                        vl[x] = V[(size_t)ij * 32 + lane];   // coalesced row
                        sp[x] = 0.f;
                    }
                    #pragma unroll
                    for (int q = 0; q < 32; q++) {
                        #pragma unroll
                        for (int x = 0; x < 8; x++) {
                            float vq = __shfl_sync(0xffffffffu, vl[x], q);
                            sp[x] = fmaf(w[q], vq, sp[x]);
                        }
                    }
                    #pragma unroll
                    for (int x = 0; x < 8; x++) sp[x] *= up[x];
                    #pragma unroll
                    for (int off = 16; off > 0; off >>= 1) {
                        #pragma unroll
                        for (int x = 0; x < 8; x++)
                            sp[x] += __shfl_xor_sync(0xffffffffu, sp[x], off);
                    }
                    #pragma unroll
                    for (int x = 0; x < 8; x++)
                        if (lane == s + x && s + x < rem) out[s4.x] = sp[x];
                }
            }
        }
    }
}

extern "C" void kernel_launch(void* const* d_in, const int* in_sizes, int n_in,
                              void* d_out, int out_size)
{
    const int*   i_in = (const int*)d_in[0];
    const int*   j_in = (const int*)d_in[1];
    const int*   k_in = (const int*)d_in[2];
    const float* U    = (const float*)d_in[3];
    const float* V    = (const float*)d_in[4];
    const float* T    = (const float*)d_in[5];
    const float* C    = (const float*)d_in[6];
    float*       out  = (float*)d_out;

    const int n = in_sizes[0];

    static bool configured = false;
    if (!configured) {
        cudaFuncSetAttribute(tucker_main,
                             cudaFuncAttributeMaxDynamicSharedMemorySize,
                             SMEM_BYTES);
        configured = true;
    }

    scatter_kernel<<<(n + 255) / 256, 256>>>(k_in, i_in, j_in, n);
    tucker_main<<<NUM_CTAS, CTA_THREADS, SMEM_BYTES>>>(i_in, j_in, k_in,
                                                       U, V, T, C, out);
}